// round 3
// baseline (speedup 1.0000x reference)
#include <cuda_runtime.h>

#define ITERS 100
#define EPSF  1e-12f

__device__ __forceinline__ float squashf(float x) {
    // 0.02 + 0.96 * sigmoid(x)
    float s = __fdividef(1.0f, 1.0f + __expf(-x));
    return fmaf(0.96f, s, 0.02f);
}

__global__ void __launch_bounds__(256) sk_kernel(
    const float* __restrict__ margins,
    const float* __restrict__ W1, const float* __restrict__ b1,
    const float* __restrict__ W2, const float* __restrict__ b2,
    const float* __restrict__ W3, const float* __restrict__ b3,
    const float* __restrict__ Wtau,
    float* __restrict__ out, int B)
{
    __shared__ __align__(16) float sW1[12 * 32];
    __shared__ __align__(16) float sW2[32 * 16];
    __shared__ __align__(16) float sW3[16 * 18];
    __shared__ __align__(16) float sWt[8 * 36];
    __shared__ __align__(16) float sb1[32];
    __shared__ __align__(16) float sb2[16];
    __shared__ __align__(16) float sb3[18];

    const int t = threadIdx.x;
    for (int i = t; i < 384; i += 256) sW1[i] = W1[i];
    for (int i = t; i < 512; i += 256) sW2[i] = W2[i];
    for (int i = t; i < 288; i += 256) sW3[i] = W3[i];
    for (int i = t; i < 288; i += 256) sWt[i] = Wtau[i];
    if (t < 32) sb1[t] = b1[t];
    if (t < 16) sb2[t] = b2[t];
    if (t < 18) sb3[t] = b3[t];
    __syncthreads();

    const int b = blockIdx.x * 256 + t;
    if (b >= B) return;

    // ---- margins: 12 floats, 16B-aligned per row ----
    float m[12];
    {
        const float4* mv = (const float4*)margins + (size_t)b * 3;
        float4 q0 = mv[0], q1 = mv[1], q2 = mv[2];
        m[0] = q0.x; m[1] = q0.y; m[2]  = q0.z; m[3]  = q0.w;
        m[4] = q1.x; m[5] = q1.y; m[6]  = q1.z; m[7]  = q1.w;
        m[8] = q2.x; m[9] = q2.y; m[10] = q2.z; m[11] = q2.w;
    }

    // ---- MLP layer 1: 12 -> 32, relu ----
    float h[32];
#pragma unroll
    for (int j = 0; j < 32; j++) h[j] = sb1[j];
#pragma unroll
    for (int k = 0; k < 12; k++) {
        float x = m[k];
#pragma unroll
        for (int j = 0; j < 32; j++) h[j] = fmaf(x, sW1[k * 32 + j], h[j]);
    }
#pragma unroll
    for (int j = 0; j < 32; j++) h[j] = fmaxf(h[j], 0.0f);

    // ---- MLP layer 2: 32 -> 16, relu ----
    float g[16];
#pragma unroll
    for (int j = 0; j < 16; j++) g[j] = sb2[j];
#pragma unroll
    for (int k = 0; k < 32; k++) {
        float x = h[k];
#pragma unroll
        for (int j = 0; j < 16; j++) g[j] = fmaf(x, sW2[k * 16 + j], g[j]);
    }
#pragma unroll
    for (int j = 0; j < 16; j++) g[j] = fmaxf(g[j], 0.0f);

    // ---- MLP layer 3: 16 -> 18 ----
    float p[18];
#pragma unroll
    for (int j = 0; j < 18; j++) p[j] = sb3[j];
#pragma unroll
    for (int k = 0; k < 16; k++) {
        float x = g[k];
#pragma unroll
        for (int j = 0; j < 18; j++) p[j] = fmaf(x, sW3[k * 18 + j], p[j]);
    }

    float* o = out + (size_t)b * 49;

    // ---- marginals (squash) ----
    float rm[6], cm[6];
    {
        float shm[6], shf[6];
        shm[0] = squashf(p[9]);  shm[1] = squashf(p[10]); shm[2] = 1.0f;
        shm[3] = squashf(p[11]); shm[4] = squashf(p[12]); shm[5] = 1.0f;
        shf[0] = squashf(p[13]); shf[1] = squashf(p[14]); shf[2] = 1.0f;
        shf[3] = squashf(p[15]); shf[4] = squashf(p[16]); shf[5] = 1.0f;
#pragma unroll
        for (int i = 0; i < 6; i++) {
            rm[i] = m[i] * shm[i];
            cm[i] = m[6 + i] * shf[i];
            o[i * 7 + 6] = m[i]     - rm[i];  // mum0 = M*(1-shm)
            o[42 + i]    = m[6 + i] - cm[i];  // mu0f = F*(1-shf)
        }
        o[48] = 0.0f;
        out[(size_t)B * 49 + b] = __expf(p[17]);  // V
    }

    // ---- A0 = exp(einsum(pars[0:8], Wtau)) ----
    float A[36];
#pragma unroll
    for (int e = 0; e < 36; e++) {
        float d = 0.0f;
#pragma unroll
        for (int k = 0; k < 8; k++) d = fmaf(p[k], sWt[k * 36 + e], d);
        A[e] = __expf(d);
    }

    // ---- factored Sinkhorn: A_t = A0 (.) outer(R, C), A0 constant.
    // R,C are rebalanced every iteration (A-invariant) to prevent the
    // individual factors from overflowing f32 when sum(rm) != sum(cm).
    float R[6], C[6];
#pragma unroll
    for (int i = 0; i < 6; i++) { R[i] = 1.0f; C[i] = 1.0f; }

#pragma unroll 1
    for (int it = 0; it < ITERS; ++it) {
        // row step: R_i *= rm_i / (R_i * sum_j A0_ij C_j + eps)
#pragma unroll
        for (int i = 0; i < 6; i++) {
            float u = A[i * 6 + 0] * C[0];
#pragma unroll
            for (int j = 1; j < 6; j++) u = fmaf(A[i * 6 + j], C[j], u);
            u = fmaf(R[i], u, EPSF);
            R[i] = R[i] * rm[i] * __fdividef(1.0f, u);
        }
        // col step: C_j *= cm_j / (C_j * sum_i A0_ij R_i + eps)  (new R)
#pragma unroll
        for (int j = 0; j < 6; j++) {
            float v = A[j] * R[0];
#pragma unroll
            for (int i = 1; i < 6; i++) v = fmaf(A[i * 6 + j], R[i], v);
            v = fmaf(C[j], v, EPSF);
            C[j] = C[j] * cm[j] * __fdividef(1.0f, v);
        }
        // rebalance: R *= C[0], C /= C[0]  (leaves A = A0.outer(R,C) invariant)
        {
            float c0 = C[0];
            float s  = __fdividef(1.0f, c0);
#pragma unroll
            for (int i = 0; i < 6; i++) R[i] *= c0;
            C[0] = 1.0f;
#pragma unroll
            for (int j = 1; j < 6; j++) C[j] *= s;
        }
    }

    // ---- final 6x6 block of mus ----
#pragma unroll
    for (int i = 0; i < 6; i++) {
        float Ri = R[i];
#pragma unroll
        for (int j = 0; j < 6; j++)
            o[i * 7 + j] = A[i * 6 + j] * Ri * C[j];
    }
}

extern "C" void kernel_launch(void* const* d_in, const int* in_sizes, int n_in,
                              void* d_out, int out_size) {
    const float* margins = (const float*)d_in[0];
    const float* W1   = (const float*)d_in[1];
    const float* b1   = (const float*)d_in[2];
    const float* W2   = (const float*)d_in[3];
    const float* b2   = (const float*)d_in[4];
    const float* W3   = (const float*)d_in[5];
    const float* b3   = (const float*)d_in[6];
    const float* Wtau = (const float*)d_in[7];

    int B = in_sizes[0] / 12;
    int blocks = (B + 255) / 256;
    sk_kernel<<<blocks, 256>>>(margins, W1, b1, W2, b2, W3, b3, Wtau,
                               (float*)d_out, B);
}